// round 6
// baseline (speedup 1.0000x reference)
#include <cuda_runtime.h>

// Problem constants
//   x  : [B=8, Ci=32, T=128, X=256, P=3]  float32
//   w* : [Ci=32, Co=32, M1=16, M2=16, M3=3] float32
//   out: [B=8, Co=32, T=128, X=256, P=3]  float32
//
// Active spectral modes: kt in {0..15} (w1) and {112..127} (w2),
// kx in {0..15}, kz in {0,1}. lane = kx*2 + z packs the 32 (kx,z) pairs.

#define NROW 32768               // B*Ci*T = B*Co*T
#define SQ3H 0.8660254037844386f // sqrt(3)/2

// Scratch (device globals; allocation is banned)
static __device__ float2 g_Y[8 * 32 * 128 * 32]; // [b][ci][t][lane]   8 MB
static __device__ float2 g_Z[8 * 32 * 32 * 32];  // [b][ci][kt][lane]  2 MB
static __device__ float2 g_H[8 * 32 * 32 * 32];  // [b][co][kt][lane]  2 MB
static __device__ float2 g_A[8 * 32 * 128 * 32]; // [b][co][t][lane]   8 MB

// ---------------------------------------------------------------------------
// K1: forward p-rfft (len 3 -> kz 0,1) + x-DFT (256 -> kx 0..15), per row.
// One block per (b,ci,t) row. 8 warps; warp w handles modes k=2w, 2w+1.
// Lane l covers x = l, l+32, ..., l+224 with an incremental twiddle chain.
// ---------------------------------------------------------------------------
__global__ __launch_bounds__(256) void k_fwd_x(const float* __restrict__ x) {
    int row = blockIdx.x;
    int tid = threadIdx.x;
    __shared__ float srow[768];
    const float* xr = x + (size_t)row * 768;
    srow[tid]       = xr[tid];
    srow[tid + 256] = xr[tid + 256];
    srow[tid + 512] = xr[tid + 512];
    __syncthreads();

    int warp = tid >> 5, lane = tid & 31;
    float acc[2][4];
#pragma unroll
    for (int m = 0; m < 2; m++)
#pragma unroll
        for (int j = 0; j < 4; j++) acc[m][j] = 0.0f;

    // twiddle = e^{-2*pi*i * k * x / 256}; chain step = e^{-2*pi*i*k*32/256}
    float cr[2], cim[2], sr[2], sim[2];
#pragma unroll
    for (int m = 0; m < 2; m++) {
        int k = 2 * warp + m;
        sincospif(-(float)(k * lane) / 128.0f, &cim[m], &cr[m]);
        sincospif(-(float)k / 4.0f, &sim[m], &sr[m]);
    }

#pragma unroll
    for (int it = 0; it < 8; it++) {
        int xi = lane + 32 * it;
        float a = srow[3 * xi + 0];
        float b = srow[3 * xi + 1];
        float c = srow[3 * xi + 2];
        // length-3 rfft over p: kz=0 real, kz=1 complex (w = e^{-2pi i/3})
        float f0  = a + b + c;
        float f1r = a - 0.5f * (b + c);
        float f1i = SQ3H * (c - b);
#pragma unroll
        for (int m = 0; m < 2; m++) {
            float wr = cr[m], wi = cim[m];
            acc[m][0] += f0 * wr;
            acc[m][1] += f0 * wi;
            acc[m][2] += f1r * wr - f1i * wi;
            acc[m][3] += f1r * wi + f1i * wr;
            float nr = wr * sr[m] - wi * sim[m];
            float ni = wr * sim[m] + wi * sr[m];
            cr[m] = nr; cim[m] = ni;
        }
    }

    // warp-reduce 8 floats
#pragma unroll
    for (int off = 16; off; off >>= 1)
#pragma unroll
        for (int m = 0; m < 2; m++)
#pragma unroll
            for (int j = 0; j < 4; j++)
                acc[m][j] += __shfl_xor_sync(0xffffffffu, acc[m][j], off);

    if (lane == 0) {
#pragma unroll
        for (int m = 0; m < 2; m++) {
            int k = 2 * warp + m;
            g_Y[(size_t)row * 32 + k * 2 + 0] = make_float2(acc[m][0], acc[m][1]);
            g_Y[(size_t)row * 32 + k * 2 + 1] = make_float2(acc[m][2], acc[m][3]);
        }
    }
}

// ---------------------------------------------------------------------------
// K2: forward t-DFT: 128 t -> 32 kt (global rows kt<16 -> kt, kt>=16 -> 96+kt).
// One warp per (b,ci,kt); lanes = the 32 (kx,z) pairs (coalesced).
// ---------------------------------------------------------------------------
__global__ __launch_bounds__(256) void k_fwd_t() {
    int g    = (blockIdx.x * 256 + threadIdx.x) >> 5; // 0..8191
    int lane = threadIdx.x & 31;
    int kt = g & 31, ci = (g >> 5) & 31, b = g >> 10;
    int freq = (kt < 16) ? kt : (96 + kt); // 112..127 for upper corner

    float sr, si;
    sincospif(-(float)freq / 64.0f, &si, &sr); // e^{-2pi i freq/128}
    float wr = 1.0f, wi = 0.0f;
    float ar = 0.0f, ai = 0.0f;
    const float2* Yp = g_Y + (size_t)(b * 32 + ci) * 4096 + lane;
#pragma unroll 8
    for (int t = 0; t < 128; t++) {
        float2 v = Yp[t * 32];
        ar += v.x * wr - v.y * wi;
        ai += v.x * wi + v.y * wr;
        float nr = wr * sr - wi * si;
        float ni = wr * si + wi * sr;
        wr = nr; wi = ni;
    }
    g_Z[((size_t)(b * 32 + ci) * 32 + kt) * 32 + lane] = make_float2(ar, ai);
}

// ---------------------------------------------------------------------------
// K3: channel mix: H[b,co,kt,kx,z] = sum_ci Z[b,ci,kt,kx,z] * w[ci,co,j,kx,z]
// (w1 for kt<16 with j=kt, w2 for kt>=16 with j=kt-16). Thread per output.
// ---------------------------------------------------------------------------
__global__ __launch_bounds__(256) void k_mix(const float* __restrict__ w1r,
                                             const float* __restrict__ w1i,
                                             const float* __restrict__ w2r,
                                             const float* __restrict__ w2i) {
    int idx  = blockIdx.x * 256 + threadIdx.x; // 0..262143 == H linear index
    int lane = idx & 31;
    int kt   = (idx >> 5) & 31;
    int co   = (idx >> 10) & 31;
    int b    = idx >> 15;
    int kx = lane >> 1, z = lane & 1;

    const float* wr = (kt < 16) ? w1r : w2r;
    const float* wi = (kt < 16) ? w1i : w2i;
    int j     = kt & 15;
    int wbase = co * 768 + j * 48 + kx * 3 + z; // + ci*24576

    float ar = 0.0f, ai = 0.0f;
    const float2* Zp = g_Z + (size_t)b * 32768 + (size_t)kt * 32 + lane; // + ci*1024
#pragma unroll 4
    for (int ci = 0; ci < 32; ci++) {
        float2 zv = Zp[ci * 1024];
        float  wre = wr[wbase + ci * 24576];
        float  wim = wi[wbase + ci * 24576];
        ar += zv.x * wre - zv.y * wim;
        ai += zv.x * wim + zv.y * wre;
    }
    g_H[idx] = make_float2(ar, ai);
}

// ---------------------------------------------------------------------------
// K4: inverse t-DFT: 32 kt modes -> 128 t. One warp per (b,co,t).
// Two twiddle chains (low corner from 1, high corner from e^{2pi i*112 t/128}).
// ---------------------------------------------------------------------------
__global__ __launch_bounds__(256) void k_inv_t() {
    int g    = (blockIdx.x * 256 + threadIdx.x) >> 5; // 0..32767
    int lane = threadIdx.x & 31;
    int t = g & 127, co = (g >> 7) & 31, b = g >> 12;

    float s1r, s1i;
    sincospif((float)t / 64.0f, &s1i, &s1r); // e^{+2pi i t/128}
    float ar = 0.0f, ai = 0.0f;
    const float2* Hp = g_H + (size_t)(b * 32 + co) * 1024 + lane;

    float wr = 1.0f, wi = 0.0f;
#pragma unroll
    for (int kt = 0; kt < 16; kt++) {
        float2 h = Hp[kt * 32];
        ar += h.x * wr - h.y * wi;
        ai += h.x * wi + h.y * wr;
        float nr = wr * s1r - wi * s1i;
        float ni = wr * s1i + wi * s1r;
        wr = nr; wi = ni;
    }
    // high corner: start at e^{2pi i * 112 * t/128} = sincospi(1.75*t)
    sincospif(1.75f * (float)t, &wi, &wr);
#pragma unroll
    for (int kt = 16; kt < 32; kt++) {
        float2 h = Hp[kt * 32];
        ar += h.x * wr - h.y * wi;
        ai += h.x * wi + h.y * wr;
        float nr = wr * s1r - wi * s1i;
        float ni = wr * s1i + wi * s1r;
        wr = nr; wi = ni;
    }
    g_A[((size_t)(b * 32 + co) * 128 + t) * 32 + lane] = make_float2(ar, ai);
}

// ---------------------------------------------------------------------------
// K5: inverse x-DFT (16 kx -> 256 x) + length-3 irfft over p + store.
// One block per (b,co,t) row; thread = x. A row staged in smem (broadcast).
// irfft(n=3): out_p = (1/N) * (Re(S0) + 2*Re(S1 * e^{2pi i p/3})).
// ---------------------------------------------------------------------------
__global__ __launch_bounds__(256) void k_inv_x(float* __restrict__ out) {
    int row = blockIdx.x;
    int tid = threadIdx.x; // x
    __shared__ float2 sA[32];
    if (tid < 32) sA[tid] = g_A[(size_t)row * 32 + tid];
    __syncthreads();

    float sr, si;
    sincospif((float)tid / 128.0f, &si, &sr); // e^{+2pi i x/256}
    float wr = 1.0f, wi = 0.0f;
    float S0r = 0.0f, S1r = 0.0f, S1i = 0.0f;
#pragma unroll
    for (int kx = 0; kx < 16; kx++) {
        float2 a0 = sA[kx * 2 + 0];
        float2 a1 = sA[kx * 2 + 1];
        S0r += a0.x * wr - a0.y * wi; // Im(S0) discarded by irfft -> not computed
        S1r += a1.x * wr - a1.y * wi;
        S1i += a1.x * wi + a1.y * wr;
        float nr = wr * sr - wi * si;
        float ni = wr * si + wi * sr;
        wr = nr; wi = ni;
    }
    const float inv = 1.0f / 98304.0f; // 1/(T*X*P)
    float p0 = (S0r + 2.0f * S1r) * inv;
    float p1 = (S0r + 2.0f * (-0.5f * S1r - SQ3H * S1i)) * inv;
    float p2 = (S0r + 2.0f * (-0.5f * S1r + SQ3H * S1i)) * inv;
    size_t o = ((size_t)row * 256 + tid) * 3;
    out[o + 0] = p0;
    out[o + 1] = p1;
    out[o + 2] = p2;
}

// ---------------------------------------------------------------------------
extern "C" void kernel_launch(void* const* d_in, const int* in_sizes, int n_in,
                              void* d_out, int out_size) {
    const float* x   = (const float*)d_in[0];
    const float* w1r = (const float*)d_in[1];
    const float* w1i = (const float*)d_in[2];
    const float* w2r = (const float*)d_in[3];
    const float* w2i = (const float*)d_in[4];
    float* out = (float*)d_out;

    k_fwd_x<<<NROW, 256>>>(x);                   // [b,ci,t] rows
    k_fwd_t<<<1024, 256>>>();                    // 8192 warps
    k_mix<<<1024, 256>>>(w1r, w1i, w2r, w2i);    // 262144 outputs
    k_inv_t<<<4096, 256>>>();                    // 32768 warps
    k_inv_x<<<NROW, 256>>>(out);                 // [b,co,t] rows
}

// round 8
// speedup vs baseline: 1.8469x; 1.8469x over previous
#include <cuda_runtime.h>

// Problem constants
//   x  : [B=8, Ci=32, T=128, X=256, P=3]  float32
//   w* : [Ci=32, Co=32, M1=16, M2=16, M3=3] float32
//   out: [B=8, Co=32, T=128, X=256, P=3]  float32
//
// Active spectral modes: kt in {0..15} (w1) and {112..127} (w2),
// kx in {0..15}, kz in {0,1}. lane = kx*2 + z packs the 32 (kx,z) pairs.

#define SQ3H 0.8660254037844386f // sqrt(3)/2

typedef unsigned long long u64;

// ---- packed f32x2 helpers (FFMA2 path) ------------------------------------
__device__ __forceinline__ u64 pk2(float lo, float hi) {
    u64 r; asm("mov.b64 %0, {%1, %2};" : "=l"(r) : "f"(lo), "f"(hi)); return r;
}
__device__ __forceinline__ void up2(u64 v, float& lo, float& hi) {
    asm("mov.b64 {%0, %1}, %2;" : "=f"(lo), "=f"(hi) : "l"(v));
}
__device__ __forceinline__ u64 fma2(u64 a, u64 b, u64 c) {
    u64 d; asm("fma.rn.f32x2 %0, %1, %2, %3;" : "=l"(d) : "l"(a), "l"(b), "l"(c)); return d;
}
__device__ __forceinline__ u64 mul2(u64 a, u64 b) {
    u64 d; asm("mul.rn.f32x2 %0, %1, %2;" : "=l"(d) : "l"(a), "l"(b)); return d;
}
// dup-packed complex twiddle chain step: w *= s  (both halves identical dups)
__device__ __forceinline__ void cstep(u64& wpp, u64& wqq, u64 spp, u64 sqq, u64 sqn) {
    u64 t1 = mul2(wqq, sqn);          // -wi*si
    u64 np = fma2(wpp, spp, t1);      // wr' = wr*sr - wi*si
    u64 t2 = mul2(wqq, spp);          //  wi*sr
    wqq    = fma2(wpp, sqq, t2);      // wi' = wr*si + wi*sr
    wpp    = np;
}

// Scratch (device globals; allocation is banned)
static __device__ float2 g_Y[8 * 32 * 128 * 32]; // [b][ci][t][lane]   8 MB
static __device__ float2 g_Z[8 * 32 * 32 * 32];  // [b][ci][kt][lane]  2 MB
static __device__ float2 g_H[8 * 32 * 32 * 32];  // [b][co][kt][lane]  2 MB
static __device__ float2 g_A[8 * 32 * 128 * 32]; // [b][co][t][lane]   8 MB

// twiddle tables, stored dup-packed (wr,wr,wi,wi)
static __device__ float4 g_Tf[32 * 128]; // fwd t: [kt][t]  e^{-2pi i freq(kt) t/128}
static __device__ float4 g_Ti[64 * 32];  // inv t: [t][kt]  e^{+2pi i freq(kt) t/128}

// ---------------------------------------------------------------------------
// K0: build twiddle tables (tiny; runs every launch, deterministic)
// ---------------------------------------------------------------------------
__global__ void k_tw() {
    int i = blockIdx.x * 256 + threadIdx.x;
    if (i < 4096) {
        int kt = i >> 7, t = i & 127;
        int f = (kt < 16) ? kt : 96 + kt;
        float s, c; sincospif(-(float)(f * t) / 64.0f, &s, &c);
        g_Tf[i] = make_float4(c, c, s, s);
    } else if (i < 4096 + 2048) {
        int j = i - 4096; int t = j >> 5, kt = j & 31;
        int f = (kt < 16) ? kt : 96 + kt;
        float s, c; sincospif((float)(f * t) / 64.0f, &s, &c);
        g_Ti[j] = make_float4(c, c, s, s);
    }
}

// ---------------------------------------------------------------------------
// K1: forward p-rfft + x-DFT, lane-parallel with radix-4 DIF over x.
// Block = 8 rows. Phase 1: per x0<64, combine x0,x0+64,x0+128,x0+192 into the
// four k-mod-4 classes (c0, D1, c2, D3) for both the f0 and f1 channels.
// Phase 2: warp per row; lane = (kx,z) output; 64-step dup-packed chain,
// quadrature accumulation; NO warp reduction, NO shfl.
// ---------------------------------------------------------------------------
__global__ __launch_bounds__(256) void k_fwd_x(const float* __restrict__ x) {
    __shared__ __align__(16) float2 sD[8][64][8]; // 32 KB
    int row0 = blockIdx.x * 8;
    int tid = threadIdx.x;

#pragma unroll
    for (int tsk = 0; tsk < 2; tsk++) {
        int task = tid + 256 * tsk; // 0..511
        int rl = task >> 6;
        int x0 = task & 63;
        const float* xp = x + (size_t)(row0 + rl) * 768 + 3 * x0;
        float f0[4], f1r[4], f1i[4];
#pragma unroll
        for (int j = 0; j < 4; j++) {
            float a = xp[192 * j + 0], b = xp[192 * j + 1], c = xp[192 * j + 2];
            float s = b + c;
            f0[j]  = a + s;
            f1r[j] = fmaf(-0.5f, s, a);
            f1i[j] = SQ3H * (c - b);
        }
        // f0 channel (real)
        float s02 = f0[0] + f0[2], s13 = f0[1] + f0[3];
        float p0 = f0[0] - f0[2], m0 = f0[1] - f0[3];
        // f1 channel (complex)
        float r02 = f1r[0] + f1r[2], r13 = f1r[1] + f1r[3];
        float i02 = f1i[0] + f1i[2], i13 = f1i[1] + f1i[3];
        float pr = f1r[0] - f1r[2], mr = f1r[1] - f1r[3];
        float pi = f1i[0] - f1i[2], mi = f1i[1] - f1i[3];
        float2* d = sD[rl][x0];
        d[0] = make_float2(s02 + s13, 0.0f);      // class 0, f0
        d[1] = make_float2(p0, -m0);              // class 1, f0 : P - iM
        d[2] = make_float2(s02 - s13, 0.0f);      // class 2, f0
        d[3] = make_float2(p0, m0);               // class 3, f0 : P + iM
        d[4] = make_float2(r02 + r13, i02 + i13); // class 0, f1
        d[5] = make_float2(pr + mi, pi - mr);     // class 1, f1 : Pc - i Mc
        d[6] = make_float2(r02 - r13, i02 - i13); // class 2, f1
        d[7] = make_float2(pr - mi, pi + mr);     // class 3, f1 : Pc + i Mc
    }
    __syncthreads();

    int warp = tid >> 5, lane = tid & 31;
    int kx = lane >> 1, z = lane & 1;
    int slot = (z << 2) | (kx & 3);

    float sr, si; sincospif(-(float)kx / 128.0f, &si, &sr); // e^{-2pi i kx/256}
    u64 spp = pk2(sr, sr), sqq = pk2(si, si), sqn = pk2(-si, -si);
    u64 wpp = pk2(1.0f, 1.0f), wqq = pk2(0.0f, 0.0f);
    u64 U = 0ull, V = 0ull;
    const u64* dp = reinterpret_cast<const u64*>(&sD[warp][0][slot]);
#pragma unroll 16
    for (int xp = 0; xp < 64; xp++) {
        u64 v = dp[xp * 8];
        U = fma2(v, wpp, U);
        V = fma2(v, wqq, V);
        cstep(wpp, wqq, spp, sqq, sqn);
    }
    float ua, ub, va, vb; up2(U, ua, ub); up2(V, va, vb);
    g_Y[(size_t)(row0 + warp) * 32 + lane] = make_float2(ua - vb, va + ub);
}

// ---------------------------------------------------------------------------
// K2: forward t-DFT: 128 t -> 32 kt. Warp per (b,ci,kt); packed + table.
// ---------------------------------------------------------------------------
__global__ __launch_bounds__(256) void k_fwd_t() {
    int g    = (blockIdx.x * 256 + threadIdx.x) >> 5; // 0..8191
    int lane = threadIdx.x & 31;
    int kt = g & 31, ci = (g >> 5) & 31, b = g >> 10;

    const u64* Yp = reinterpret_cast<const u64*>(g_Y) + (size_t)(b * 32 + ci) * 4096 + lane;
    const ulonglong2* T = reinterpret_cast<const ulonglong2*>(g_Tf) + kt * 128;
    u64 U = 0ull, V = 0ull;
#pragma unroll 8
    for (int t = 0; t < 128; t++) {
        u64 v = Yp[(size_t)t * 32];
        ulonglong2 w = T[t]; // (wr,wr | wi,wi), uniform across warp
        U = fma2(v, w.x, U);
        V = fma2(v, w.y, V);
    }
    float ua, ub, va, vb; up2(U, ua, ub); up2(V, va, vb);
    g_Z[((size_t)(b * 32 + ci) * 32 + kt) * 32 + lane] = make_float2(ua - vb, va + ub);
}

// ---------------------------------------------------------------------------
// K3: channel mix: H = sum_ci Z * w  (w1 for kt<16 j=kt, w2 for kt>=16 j=kt-16)
// ---------------------------------------------------------------------------
__global__ __launch_bounds__(256) void k_mix(const float* __restrict__ w1r,
                                             const float* __restrict__ w1i,
                                             const float* __restrict__ w2r,
                                             const float* __restrict__ w2i) {
    int idx  = blockIdx.x * 256 + threadIdx.x; // H linear index
    int lane = idx & 31;
    int kt   = (idx >> 5) & 31;
    int co   = (idx >> 10) & 31;
    int b    = idx >> 15;
    int kx = lane >> 1, z = lane & 1;

    const float* wr = (kt < 16) ? w1r : w2r;
    const float* wi = (kt < 16) ? w1i : w2i;
    int j     = kt & 15;
    int wbase = co * 768 + j * 48 + kx * 3 + z;

    float ar = 0.0f, ai = 0.0f;
    const float2* Zp = g_Z + (size_t)b * 32768 + (size_t)kt * 32 + lane;
#pragma unroll 4
    for (int ci = 0; ci < 32; ci++) {
        float2 zv = Zp[ci * 1024];
        float  wre = wr[wbase + ci * 24576];
        float  wim = wi[wbase + ci * 24576];
        ar += zv.x * wre - zv.y * wim;
        ai += zv.x * wim + zv.y * wre;
    }
    g_H[idx] = make_float2(ar, ai);
}

// ---------------------------------------------------------------------------
// K4: inverse t-DFT with t / t+64 parity symmetry. Warp per (b,co,t0<64);
// even/odd-kt partial sums produce outputs at t0 and t0+64.
// ---------------------------------------------------------------------------
__global__ __launch_bounds__(256) void k_inv_t() {
    int g    = (blockIdx.x * 256 + threadIdx.x) >> 5; // 0..16383
    int lane = threadIdx.x & 31;
    int t0 = g & 63, co = (g >> 6) & 31, b = g >> 11;

    const u64* Hp = reinterpret_cast<const u64*>(g_H) + (size_t)(b * 32 + co) * 1024 + lane;
    const ulonglong2* T = reinterpret_cast<const ulonglong2*>(g_Ti) + t0 * 32;
    u64 U0 = 0ull, V0 = 0ull, U1 = 0ull, V1 = 0ull;
#pragma unroll
    for (int kt = 0; kt < 32; kt += 2) {
        u64 v0 = Hp[(size_t)kt * 32];
        ulonglong2 w0 = T[kt];
        U0 = fma2(v0, w0.x, U0); V0 = fma2(v0, w0.y, V0);
        u64 v1 = Hp[(size_t)(kt + 1) * 32];
        ulonglong2 w1 = T[kt + 1];
        U1 = fma2(v1, w1.x, U1); V1 = fma2(v1, w1.y, V1);
    }
    float a, bb, c, d;
    up2(U0, a, bb); up2(V0, c, d); float er = a - d, ei = c + bb;
    up2(U1, a, bb); up2(V1, c, d); float orr = a - d, oi = c + bb;
    size_t base = (size_t)(b * 32 + co) * 128;
    g_A[(base + t0) * 32 + lane]      = make_float2(er + orr, ei + oi);
    g_A[(base + t0 + 64) * 32 + lane] = make_float2(er - orr, ei - oi);
}

// ---------------------------------------------------------------------------
// K5: inverse x-DFT + irfft(p=3) + store. Thread = x0<64 of a row; radix-4
// group accumulators amortize one 16-step chain over outputs at
// x0, x0+64, x0+128, x0+192. Block = 4 rows.
// ---------------------------------------------------------------------------
__global__ __launch_bounds__(256) void k_inv_x(float* __restrict__ out) {
    __shared__ __align__(16) float2 sA[128]; // 4 rows x 32 coeffs
    int tid = threadIdx.x;
    size_t row0 = (size_t)blockIdx.x * 4;
    if (tid < 128) sA[tid] = g_A[row0 * 32 + tid];
    __syncthreads();

    int rl = tid >> 6, x0 = tid & 63;
    const ulonglong2* Ap = reinterpret_cast<const ulonglong2*>(sA) + rl * 16;

    float sr, si; sincospif((float)x0 / 128.0f, &si, &sr); // e^{+2pi i x0/256}
    u64 spp = pk2(sr, sr), sqq = pk2(si, si), sqn = pk2(-si, -si);
    u64 wpp = pk2(1.0f, 1.0f), wqq = pk2(0.0f, 0.0f);
    u64 A0[4] = {0,0,0,0}, B0[4] = {0,0,0,0}, A1[4] = {0,0,0,0}, B1[4] = {0,0,0,0};
#pragma unroll
    for (int k = 0; k < 16; k++) {
        ulonglong2 q = Ap[k]; // (a0 | a1) for this kx, uniform per 64 threads
        int gI = k & 3;
        A0[gI] = fma2(q.x, wpp, A0[gI]); B0[gI] = fma2(q.x, wqq, B0[gI]);
        A1[gI] = fma2(q.y, wpp, A1[gI]); B1[gI] = fma2(q.y, wqq, B1[gI]);
        cstep(wpp, wqq, spp, sqq, sqn);
    }
    float S0r[4], S0i[4], S1r[4], S1i[4];
#pragma unroll
    for (int gi = 0; gi < 4; gi++) {
        float a, b2, c, d;
        up2(A0[gi], a, b2); up2(B0[gi], c, d); S0r[gi] = a - d; S0i[gi] = c + b2;
        up2(A1[gi], a, b2); up2(B1[gi], c, d); S1r[gi] = a - d; S1i[gi] = c + b2;
    }
    // radix-4 butterflies: S(d) = T0+T2 | T1+iT3 | T0-T2 | T1-iT3
    float T0r = S0r[0] + S0r[2], T1r = S0r[0] - S0r[2];
    float T2r = S0r[1] + S0r[3], T3r = S0r[1] - S0r[3];
    float T0i = S0i[0] + S0i[2], T1i = S0i[0] - S0i[2];
    float T2i = S0i[1] + S0i[3], T3i = S0i[1] - S0i[3];
    float U0r = S1r[0] + S1r[2], U1r = S1r[0] - S1r[2];
    float U2r = S1r[1] + S1r[3], U3r = S1r[1] - S1r[3];
    float U0i = S1i[0] + S1i[2], U1i = S1i[0] - S1i[2];
    float U2i = S1i[1] + S1i[3], U3i = S1i[1] - S1i[3];
    (void)T0i; (void)T1i; (void)T2i; (void)T3r; // only Re(S0) used (T3i needed)

    float s0[4], s1r_[4], s1i_[4];
    s0[0] = T0r + T2r; s1r_[0] = U0r + U2r; s1i_[0] = U0i + U2i; // d=0
    s0[1] = T1r - T3i; s1r_[1] = U1r - U3i; s1i_[1] = U1i + U3r; // d=64
    s0[2] = T0r - T2r; s1r_[2] = U0r - U2r; s1i_[2] = U0i - U2i; // d=128
    s0[3] = T1r + T3i; s1r_[3] = U1r + U3i; s1i_[3] = U1i - U3r; // d=192

    const float inv = 1.0f / 98304.0f; // 1/(T*X*P)
    size_t rbase = (row0 + rl) * 256;
#pragma unroll
    for (int dd = 0; dd < 4; dd++) {
        int xx = x0 + 64 * dd;
        float S0 = s0[dd], R = s1r_[dd], I = s1i_[dd];
        float p0 = (S0 + 2.0f * R) * inv;
        float p1 = (S0 + 2.0f * (-0.5f * R - SQ3H * I)) * inv;
        float p2 = (S0 + 2.0f * (-0.5f * R + SQ3H * I)) * inv;
        size_t o = (rbase + xx) * 3;
        out[o + 0] = p0;
        out[o + 1] = p1;
        out[o + 2] = p2;
    }
}

// ---------------------------------------------------------------------------
extern "C" void kernel_launch(void* const* d_in, const int* in_sizes, int n_in,
                              void* d_out, int out_size) {
    const float* x   = (const float*)d_in[0];
    const float* w1r = (const float*)d_in[1];
    const float* w1i = (const float*)d_in[2];
    const float* w2r = (const float*)d_in[3];
    const float* w2i = (const float*)d_in[4];
    float* out = (float*)d_out;

    k_tw<<<24, 256>>>();                         // twiddle tables
    k_fwd_x<<<4096, 256>>>(x);                   // 8 rows/block
    k_fwd_t<<<1024, 256>>>();                    // 8192 warps
    k_mix<<<1024, 256>>>(w1r, w1i, w2r, w2i);    // 262144 outputs
    k_inv_t<<<2048, 256>>>();                    // 16384 warps (parity split)
    k_inv_x<<<8192, 256>>>(out);                 // 4 rows/block
}